// round 14
// baseline (speedup 1.0000x reference)
#include <cuda_runtime.h>
#include <cstdint>

// Problem constants
#define NN 32768
#define DD 384
#define EE 524288
#define BBATCH 32
#define SSEQ 1024
#define HHEADS 8
#define DHEAD 48
#define FFDIM 768
#define BN_EPS 1e-5f

#define MMA_TF32(c, a0, a1, a2, a3, b0, b1) \
    asm volatile( \
        "mma.sync.aligned.m16n8k8.row.col.f32.tf32.tf32.f32 " \
        "{%0,%1,%2,%3}, {%4,%5,%6,%7}, {%8,%9}, {%0,%1,%2,%3};" \
        : "+f"((c)[0]), "+f"((c)[1]), "+f"((c)[2]), "+f"((c)[3]) \
        : "r"(a0), "r"(a1), "r"(a2), "r"(a3), "r"(b0), "r"(b1))

// ---------------- device scratch ----------------
__device__ float g_agg[(size_t)NN * DD];
__device__ float g_hl[(size_t)NN * DD];
__device__ float g_t[(size_t)NN * FFDIM];
__device__ float g_q[(size_t)NN * DD];
__device__ float g_k[(size_t)NN * DD];
__device__ float g_v[(size_t)NN * DD];
__device__ float g_o[(size_t)NN * DD];
__device__ float g_sum[2 * DD];
__device__ float g_sq[2 * DD];
__device__ float g_scale[2 * DD];
__device__ float g_shift[2 * DD];
__device__ int g_cnt[NN];
__device__ int g_start[NN];
__device__ int g_cursor[NN];
__device__ int g_eid[EE];

// ---------------- tf32 mma.sync SGEMM core: 128x128x16 tile, 8 warps ----------
// AMODE: 0 = plain A; 1 = A element = bn0(A) + bn1(A2) (combine fused in)
// RESMODE: 0 = none; 1 = plain res; 2 = res element = bn0(res) + bn1(res2)
template <bool RELU, int AMODE, int RESMODE>
__device__ __forceinline__ void gemm_body(
    const float* __restrict__ A, const float* __restrict__ A2,
    const float* __restrict__ W, const float* __restrict__ bias,
    const float* __restrict__ res, const float* __restrict__ res2,
    float* __restrict__ C, int K, int M, int colBase, size_t rowBase) {
    __shared__ uint32_t Af[2][2][8][128];
    __shared__ uint32_t Bf[2][2][16][66];

    const int tid = threadIdx.x;
    const int lane = tid & 31;
    const int wid = tid >> 5;
    const int warpRow = wid >> 2;
    const int warpCol = wid & 3;

    float acc[4][4][4];
#pragma unroll
    for (int i = 0; i < 4; i++)
#pragma unroll
        for (int j = 0; j < 4; j++)
#pragma unroll
            for (int e = 0; e < 4; e++) acc[i][j][e] = 0.f;

    const int ar = tid >> 1;
    const int akq = (tid & 1) * 8;
    const int a_kk = akq >> 3;
    const int a_mt = ar >> 4;
    const int a_g = ar & 7;
    const int a_half = (ar >> 3) & 1;
    const int bkr = tid >> 4;
    const int bnq = (tid & 15) * 8;
    const int b_kk = bkr >> 3;
    const int b_c = bkr & 7;
    const int b_slot = (b_c >= 4) ? 1 : 0;
    const int b_cm = b_c & 3;

    const float* Ap = A + (rowBase + ar) * (size_t)K + akq;
    const float* A2p = (AMODE == 1) ? (A2 + (rowBase + ar) * (size_t)K + akq) : nullptr;
    const float* Wp = W + (size_t)bkr * M + colBase + bnq;

    const int stages = K >> 4;
    float aR[8], bR[8];

    auto load_regs = [&](int s) {
        const float* Ap2 = Ap + s * 16;
        float4 t0 = *(const float4*)(Ap2);
        float4 t1 = *(const float4*)(Ap2 + 4);
        if (AMODE == 1) {
            const float* Bp2 = A2p + s * 16;
            float4 u0 = *(const float4*)(Bp2);
            float4 u1 = *(const float4*)(Bp2 + 4);
            int cb = s * 16 + akq;
            float4 sA0 = *(const float4*)&g_scale[cb];
            float4 sA1 = *(const float4*)&g_scale[cb + 4];
            float4 hA0 = *(const float4*)&g_shift[cb];
            float4 hA1 = *(const float4*)&g_shift[cb + 4];
            float4 sB0 = *(const float4*)&g_scale[DD + cb];
            float4 sB1 = *(const float4*)&g_scale[DD + cb + 4];
            float4 hB0 = *(const float4*)&g_shift[DD + cb];
            float4 hB1 = *(const float4*)&g_shift[DD + cb + 4];
            aR[0] = t0.x * sA0.x + hA0.x + u0.x * sB0.x + hB0.x;
            aR[1] = t0.y * sA0.y + hA0.y + u0.y * sB0.y + hB0.y;
            aR[2] = t0.z * sA0.z + hA0.z + u0.z * sB0.z + hB0.z;
            aR[3] = t0.w * sA0.w + hA0.w + u0.w * sB0.w + hB0.w;
            aR[4] = t1.x * sA1.x + hA1.x + u1.x * sB1.x + hB1.x;
            aR[5] = t1.y * sA1.y + hA1.y + u1.y * sB1.y + hB1.y;
            aR[6] = t1.z * sA1.z + hA1.z + u1.z * sB1.z + hB1.z;
            aR[7] = t1.w * sA1.w + hA1.w + u1.w * sB1.w + hB1.w;
        } else {
            aR[0] = t0.x; aR[1] = t0.y; aR[2] = t0.z; aR[3] = t0.w;
            aR[4] = t1.x; aR[5] = t1.y; aR[6] = t1.z; aR[7] = t1.w;
        }
        const float* Wp2 = Wp + (size_t)s * 16 * M;
        float4 u0 = *(const float4*)(Wp2);
        float4 u1 = *(const float4*)(Wp2 + 4);
        bR[0] = u0.x; bR[1] = u0.y; bR[2] = u0.z; bR[3] = u0.w;
        bR[4] = u1.x; bR[5] = u1.y; bR[6] = u1.z; bR[7] = u1.w;
    };
    auto store_stage = [&](int buf) {
#pragma unroll
        for (int j = 0; j < 8; j++) {
            int slot = ((j >= 4) ? 2 : 0) + a_half;
            if (a_kk) slot ^= 2;
            int lp = a_g + (j & 3) * 8;
            Af[buf][a_kk][a_mt][lp * 4 + slot] = __float_as_uint(aR[j]);
        }
#pragma unroll
        for (int j = 0; j < 8; j++) {
            int nl = bnq + j;
            Bf[buf][b_kk][nl >> 3][((nl & 7) * 4 + b_cm) * 2 + b_slot] =
                __float_as_uint(bR[j]);
        }
    };

    load_regs(0);
    store_stage(0);
    if (stages > 1) load_regs(1);
    __syncthreads();

    const int rp = (lane >> 2) + (lane & 3) * 8;

    for (int s = 0; s < stages; s++) {
        const int cur = s & 1;
        if (s + 1 < stages) store_stage(1 - cur);
        if (s + 2 < stages) load_regs(s + 2);
#pragma unroll
        for (int kk = 0; kk < 2; kk++) {
            uint32_t af[4][4];
            uint32_t bf[4][2];
#pragma unroll
            for (int mi = 0; mi < 4; mi++)
                *(uint4*)af[mi] = *(const uint4*)&Af[cur][kk][warpRow * 4 + mi][rp * 4];
#pragma unroll
            for (int ni = 0; ni < 4; ni++)
                *(uint2*)bf[ni] = *(const uint2*)&Bf[cur][kk][warpCol * 4 + ni][lane * 2];
#pragma unroll
            for (int mi = 0; mi < 4; mi++)
#pragma unroll
                for (int ni = 0; ni < 4; ni++) {
                    if (kk == 0) {
                        MMA_TF32(acc[mi][ni], af[mi][0], af[mi][1], af[mi][2], af[mi][3],
                                 bf[ni][0], bf[ni][1]);
                    } else {
                        MMA_TF32(acc[mi][ni], af[mi][2], af[mi][3], af[mi][0], af[mi][1],
                                 bf[ni][0], bf[ni][1]);
                    }
                }
        }
        __syncthreads();
    }

    const int g = lane >> 2, cq = lane & 3;
#pragma unroll
    for (int mi = 0; mi < 4; mi++) {
        size_t row0 = rowBase + warpRow * 64 + mi * 16 + g;
        size_t row1 = row0 + 8;
#pragma unroll
        for (int ni = 0; ni < 4; ni++) {
            int col = colBase + warpCol * 32 + ni * 8 + cq * 2;
            float2 bi = *(const float2*)(bias + col);
            float o0 = acc[mi][ni][0] + bi.x;
            float o1 = acc[mi][ni][1] + bi.y;
            float o2 = acc[mi][ni][2] + bi.x;
            float o3 = acc[mi][ni][3] + bi.y;
            if (RELU) {
                o0 = fmaxf(o0, 0.f); o1 = fmaxf(o1, 0.f);
                o2 = fmaxf(o2, 0.f); o3 = fmaxf(o3, 0.f);
            }
            if (RESMODE == 1) {
                float2 r0 = *(const float2*)(res + row0 * (size_t)M + col);
                float2 r1 = *(const float2*)(res + row1 * (size_t)M + col);
                o0 += r0.x; o1 += r0.y; o2 += r1.x; o3 += r1.y;
            } else if (RESMODE == 2) {
                float2 r0 = *(const float2*)(res + row0 * (size_t)M + col);
                float2 r1 = *(const float2*)(res + row1 * (size_t)M + col);
                float2 q0 = *(const float2*)(res2 + row0 * (size_t)M + col);
                float2 q1 = *(const float2*)(res2 + row1 * (size_t)M + col);
                float2 sA = *(const float2*)&g_scale[col];
                float2 hA = *(const float2*)&g_shift[col];
                float2 sB = *(const float2*)&g_scale[DD + col];
                float2 hB = *(const float2*)&g_shift[DD + col];
                o0 += r0.x * sA.x + hA.x + q0.x * sB.x + hB.x;
                o1 += r0.y * sA.y + hA.y + q0.y * sB.y + hB.y;
                o2 += r1.x * sA.x + hA.x + q1.x * sB.x + hB.x;
                o3 += r1.y * sA.y + hA.y + q1.y * sB.y + hB.y;
            }
            *(float2*)(C + row0 * (size_t)M + col) = make_float2(o0, o1);
            *(float2*)(C + row1 * (size_t)M + col) = make_float2(o2, o3);
        }
    }
}

template <bool RELU, int AMODE, int RESMODE>
__global__ __launch_bounds__(256) void gemm_mma_kernel(
    const float* __restrict__ A, const float* __restrict__ A2,
    const float* __restrict__ W, const float* __restrict__ bias,
    const float* __restrict__ res, const float* __restrict__ res2,
    float* __restrict__ C, int K, int M) {
    gemm_body<RELU, AMODE, RESMODE>(A, A2, W, bias, res, res2, C, K, M,
                                    blockIdx.x * 128, (size_t)blockIdx.y * 128);
}

// Fused QKV: grid.x = 9; proj = x/3 selects {Wq,Wk,Wv}->{q,k,v}, col = (x%3)*128
__global__ __launch_bounds__(256) void gemm_qkv_kernel(
    const float* __restrict__ x,
    const float* __restrict__ Wq, const float* __restrict__ bq,
    const float* __restrict__ Wk, const float* __restrict__ bk,
    const float* __restrict__ Wv, const float* __restrict__ bv,
    float* __restrict__ q, float* __restrict__ k, float* __restrict__ v) {
    int proj = blockIdx.x / 3;
    int colBase = (blockIdx.x % 3) * 128;
    const float* W = (proj == 0) ? Wq : (proj == 1) ? Wk : Wv;
    const float* bias = (proj == 0) ? bq : (proj == 1) ? bk : bv;
    float* C = (proj == 0) ? q : (proj == 1) ? k : v;
    gemm_body<false, 0, 0>(x, nullptr, W, bias, nullptr, nullptr, C, DD, DD,
                           colBase, (size_t)blockIdx.y * 128);
}

// ---------------- tf32 mma flash attention ----------------
#define ATTN_SMEM 57344
__global__ __launch_bounds__(256) void attn_mma_kernel(
    const float* __restrict__ q, const float* __restrict__ k,
    const float* __restrict__ v, float* __restrict__ o) {
    extern __shared__ uint32_t sm[];
    const int tid = threadIdx.x;
    const int lane = tid & 31, wid = tid >> 5;
    const int g = lane >> 2, cq = lane & 3;
    uint32_t* Kf = sm;
    uint32_t* Vf = sm + 3072;
    uint32_t* Pf = sm + 6144 + wid * 1024;

    const int b = blockIdx.z, h = blockIdx.y, qt = blockIdx.x;
    const float rs = 0.14433756729740643f;

    uint32_t qf[6][4];
    {
        const float* qp0 =
            q + ((size_t)(b * SSEQ + qt * 128 + wid * 16 + g)) * DD + h * DHEAD;
        const float* qp1 = qp0 + 8 * DD;
#pragma unroll
        for (int kc = 0; kc < 6; kc++) {
            qf[kc][0] = __float_as_uint(qp0[kc * 8 + cq] * rs);
            qf[kc][1] = __float_as_uint(qp1[kc * 8 + cq] * rs);
            qf[kc][2] = __float_as_uint(qp0[kc * 8 + cq + 4] * rs);
            qf[kc][3] = __float_as_uint(qp1[kc * 8 + cq + 4] * rs);
        }
    }
    float oa[6][4];
#pragma unroll
    for (int i = 0; i < 6; i++)
#pragma unroll
        for (int e = 0; e < 4; e++) oa[i][e] = 0.f;
    float l0 = 0.f, l1 = 0.f;

    const int lr = tid >> 2;
    const int ld = (tid & 3) * 12;
    const size_t kvbase = (size_t)(b * SSEQ) * DD + h * DHEAD;

    float kreg[12], vreg[12];
    {
        const float* kp = k + kvbase + (size_t)lr * DD + ld;
        const float* vp = v + kvbase + (size_t)lr * DD + ld;
#pragma unroll
        for (int j = 0; j < 3; j++) {
            *(float4*)&kreg[j * 4] = *(const float4*)(kp + j * 4);
            *(float4*)&vreg[j * 4] = *(const float4*)(vp + j * 4);
        }
    }

    for (int kt = 0; kt < SSEQ; kt += 64) {
        __syncthreads();
#pragma unroll
        for (int j = 0; j < 12; j++) {
            int d = ld + j;
            Kf[((d >> 3) * 8 + (lr >> 3)) * 64 + ((lr & 7) * 4 + (d & 3)) * 2 +
               ((d & 7) >= 4)] = __float_as_uint(kreg[j]);
            Vf[((lr >> 3) * 6 + (d >> 3)) * 64 + ((d & 7) * 4 + (lr & 3)) * 2 +
               ((lr & 7) >= 4)] = __float_as_uint(vreg[j]);
        }
        __syncthreads();
        if (kt + 64 < SSEQ) {
            const float* kp = k + kvbase + (size_t)(kt + 64 + lr) * DD + ld;
            const float* vp = v + kvbase + (size_t)(kt + 64 + lr) * DD + ld;
#pragma unroll
            for (int j = 0; j < 3; j++) {
                *(float4*)&kreg[j * 4] = *(const float4*)(kp + j * 4);
                *(float4*)&vreg[j * 4] = *(const float4*)(vp + j * 4);
            }
        }
#pragma unroll
        for (int nt = 0; nt < 8; nt++) {
            float c[4] = {0.f, 0.f, 0.f, 0.f};
#pragma unroll
            for (int kc = 0; kc < 6; kc++) {
                uint2 kb = *(const uint2*)&Kf[(kc * 8 + nt) * 64 + lane * 2];
                MMA_TF32(c, qf[kc][0], qf[kc][1], qf[kc][2], qf[kc][3], kb.x, kb.y);
            }
            float p0 = __expf(c[0]), p1 = __expf(c[1]);
            float p2 = __expf(c[2]), p3 = __expf(c[3]);
            l0 += p0 + p1;
            l1 += p2 + p3;
            int pb = nt * 128 + ((cq < 2) ? 0 : 64) + 4 * g + ((2 * cq) & 3);
            uint2 w0, w1;
            w0.x = __float_as_uint(p0); w0.y = __float_as_uint(p1);
            w1.x = __float_as_uint(p2); w1.y = __float_as_uint(p3);
            *(uint2*)&Pf[pb] = w0;
            *(uint2*)&Pf[pb + 32] = w1;
        }
        __syncwarp();
#pragma unroll
        for (int kc = 0; kc < 8; kc++) {
            uint32_t pa0 = Pf[kc * 128 + lane];
            uint32_t pa1 = Pf[kc * 128 + 32 + lane];
            uint32_t pa2 = Pf[kc * 128 + 64 + lane];
            uint32_t pa3 = Pf[kc * 128 + 96 + lane];
#pragma unroll
            for (int nt2 = 0; nt2 < 6; nt2++) {
                uint2 vb = *(const uint2*)&Vf[(kc * 6 + nt2) * 64 + lane * 2];
                MMA_TF32(oa[nt2], pa0, pa1, pa2, pa3, vb.x, vb.y);
            }
        }
    }

    l0 += __shfl_xor_sync(0xffffffff, l0, 1);
    l0 += __shfl_xor_sync(0xffffffff, l0, 2);
    l1 += __shfl_xor_sync(0xffffffff, l1, 1);
    l1 += __shfl_xor_sync(0xffffffff, l1, 2);
    float i0 = 1.f / l0, i1 = 1.f / l1;
    float* op0 = o + ((size_t)(b * SSEQ + qt * 128 + wid * 16 + g)) * DD + h * DHEAD;
    float* op1 = op0 + 8 * DD;
#pragma unroll
    for (int nt2 = 0; nt2 < 6; nt2++) {
        int col = nt2 * 8 + 2 * cq;
        *(float2*)(op0 + col) = make_float2(oa[nt2][0] * i0, oa[nt2][1] * i0);
        *(float2*)(op1 + col) = make_float2(oa[nt2][2] * i1, oa[nt2][3] * i1);
    }
}

// ---------------- CSR build ----------------
__global__ void zero_cnt_kernel() {
    int i = blockIdx.x * blockDim.x + threadIdx.x;
    g_cnt[i] = 0;
}
__global__ void count_kernel(const int* __restrict__ ei) {
    int e = blockIdx.x * blockDim.x + threadIdx.x;
    atomicAdd(&g_cnt[ei[EE + e]], 1);
}
__global__ void scan_kernel() {
    __shared__ int sh[1024];
    int t = threadIdx.x;
    int base = t * 32;
    int local[32];
    int s = 0;
#pragma unroll
    for (int i = 0; i < 8; i++) {
        int4 c4 = *(const int4*)&g_cnt[base + i * 4];
        local[i * 4 + 0] = c4.x; local[i * 4 + 1] = c4.y;
        local[i * 4 + 2] = c4.z; local[i * 4 + 3] = c4.w;
        s += c4.x + c4.y + c4.z + c4.w;
    }
    sh[t] = s;
    __syncthreads();
    for (int off = 1; off < 1024; off <<= 1) {
        int v = sh[t];
        int add = (t >= off) ? sh[t - off] : 0;
        __syncthreads();
        sh[t] = v + add;
        __syncthreads();
    }
    int run = sh[t] - s;
#pragma unroll
    for (int i = 0; i < 8; i++) {
        int4 o4;
        o4.x = run; run += local[i * 4 + 0];
        o4.y = run; run += local[i * 4 + 1];
        o4.z = run; run += local[i * 4 + 2];
        o4.w = run; run += local[i * 4 + 3];
        *(int4*)&g_start[base + i * 4] = o4;
        *(int4*)&g_cursor[base + i * 4] = o4;
    }
}
__global__ void fill_kernel(const int* __restrict__ ei) {
    int e = blockIdx.x * blockDim.x + threadIdx.x;
    int d = ei[EE + e];
    int slot = atomicAdd(&g_cursor[d], 1);
    g_eid[slot] = e;
}

__global__ __launch_bounds__(96) void agg_kernel(const float* __restrict__ x,
                                                 const int* __restrict__ ei,
                                                 const float* __restrict__ ea) {
    __shared__ int s_eid[128];
    __shared__ int s_src[128];
    int node = blockIdx.x;
    int g = threadIdx.x;
    int start = g_start[node];
    int cnt = g_cnt[node];
    float4 acc = *(const float4*)(x + (size_t)node * DD + g * 4);
    for (int baseI = 0; baseI < cnt; baseI += 128) {
        int chunk = min(cnt - baseI, 128);
        __syncthreads();
        for (int i = g; i < chunk; i += 96) {
            int e = g_eid[start + baseI + i];
            s_eid[i] = e;
            s_src[i] = ei[e];
        }
        __syncthreads();
#pragma unroll 4
        for (int i = 0; i < chunk; i++) {
            float4 xv = *(const float4*)(x + (size_t)s_src[i] * DD + g * 4);
            float4 av = *(const float4*)(ea + (size_t)s_eid[i] * DD + g * 4);
            acc.x += fmaxf(xv.x + av.x, 0.f);
            acc.y += fmaxf(xv.y + av.y, 0.f);
            acc.z += fmaxf(xv.z + av.z, 0.f);
            acc.w += fmaxf(xv.w + av.w, 0.f);
        }
    }
    *(float4*)(g_agg + (size_t)node * DD + g * 4) = acc;
}

// ---------------- BatchNorm ----------------
__global__ void zero_stats2_kernel() {
    int c = blockIdx.x * blockDim.x + threadIdx.x;
    g_sum[c] = 0.f;
    g_sq[c] = 0.f;
}
__global__ void zero_stats_kernel() {
    int c = threadIdx.x;
    g_sum[c] = 0.f;
    g_sq[c] = 0.f;
}
__global__ void bn_stats_kernel(const float* __restrict__ h, int idx) {
    int c = threadIdx.x;
    const float* p = h + (size_t)blockIdx.x * 128 * DD + c;
    float s = 0.f, q = 0.f;
#pragma unroll 4
    for (int r = 0; r < 128; r++) {
        float v = p[(size_t)r * DD];
        s += v;
        q = fmaf(v, v, q);
    }
    atomicAdd(&g_sum[idx * DD + c], s);
    atomicAdd(&g_sq[idx * DD + c], q);
}
__global__ void bn_finalize_kernel(const float* __restrict__ gamma,
                                   const float* __restrict__ beta, int idx) {
    int c = threadIdx.x;
    float mean = g_sum[idx * DD + c] * (1.f / NN);
    float var = g_sq[idx * DD + c] * (1.f / NN) - mean * mean;
    float sc = gamma[c] * rsqrtf(var + BN_EPS);
    g_scale[idx * DD + c] = sc;
    g_shift[idx * DD + c] = beta[c] - mean * sc;
}
__global__ void bn_apply_kernel(float* __restrict__ h) {
    size_t gid = (size_t)blockIdx.x * blockDim.x + threadIdx.x;
    int c = (int)(gid % (DD / 4)) << 2;
    float4 v = ((float4*)h)[gid];
    float4 s = *(const float4*)&g_scale[c];
    float4 sh = *(const float4*)&g_shift[c];
    v.x = v.x * s.x + sh.x;
    v.y = v.y * s.y + sh.y;
    v.z = v.z * s.z + sh.z;
    v.w = v.w * s.w + sh.w;
    ((float4*)h)[gid] = v;
}

// ---------------- launch ----------------
extern "C" void kernel_launch(void* const* d_in, const int* in_sizes, int n_in,
                              void* d_out, int out_size) {
    const float* x = (const float*)d_in[0];
    const int* ei = (const int*)d_in[1];
    const float* ea = (const float*)d_in[2];
    const float* W1 = (const float*)d_in[4];
    const float* b1 = (const float*)d_in[5];
    const float* W2 = (const float*)d_in[6];
    const float* b2 = (const float*)d_in[7];
    const float* g1l = (const float*)d_in[8];
    const float* be1l = (const float*)d_in[9];
    const float* Wq = (const float*)d_in[10];
    const float* bq = (const float*)d_in[11];
    const float* Wk = (const float*)d_in[12];
    const float* bk = (const float*)d_in[13];
    const float* Wv = (const float*)d_in[14];
    const float* bv = (const float*)d_in[15];
    const float* Wo = (const float*)d_in[16];
    const float* bo = (const float*)d_in[17];
    const float* g1a = (const float*)d_in[18];
    const float* be1a = (const float*)d_in[19];
    const float* Wf1 = (const float*)d_in[20];
    const float* bf1 = (const float*)d_in[21];
    const float* Wf2 = (const float*)d_in[22];
    const float* bf2 = (const float*)d_in[23];
    const float* g2 = (const float*)d_in[24];
    const float* be2 = (const float*)d_in[25];
    float* out = (float*)d_out;

    float *agg, *hl, *t, *q, *k, *v, *o;
    cudaGetSymbolAddress((void**)&agg, g_agg);
    cudaGetSymbolAddress((void**)&hl, g_hl);
    cudaGetSymbolAddress((void**)&t, g_t);
    cudaGetSymbolAddress((void**)&q, g_q);
    cudaGetSymbolAddress((void**)&k, g_k);
    cudaGetSymbolAddress((void**)&v, g_v);
    cudaGetSymbolAddress((void**)&o, g_o);

    cudaFuncSetAttribute(attn_mma_kernel,
                         cudaFuncAttributeMaxDynamicSharedMemorySize, ATTN_SMEM);

    static cudaStream_t s2 = nullptr;
    static cudaEvent_t evF = nullptr, evJ = nullptr;
    if (s2 == nullptr) {
        cudaStreamCreate(&s2);
        cudaEventCreateWithFlags(&evF, cudaEventDisableTiming);
        cudaEventCreateWithFlags(&evJ, cudaEventDisableTiming);
    }

    const int EW_BLOCKS = (NN * DD / 4) / 256;
    const dim3 gemmD(DD / 128, NN / 128);    // (3, 256)
    const dim3 gemmQKV(9, NN / 128);         // (9, 256)
    const dim3 gemmF(FFDIM / 128, NN / 128); // (6, 256)

    zero_stats2_kernel<<<2, DD>>>();

    // ---- fork: GINE branch on s2, attention branch on default stream ----
    cudaEventRecord(evF, 0);
    cudaStreamWaitEvent(s2, evF, 0);

    // GINE branch (s2)
    zero_cnt_kernel<<<NN / 256, 256, 0, s2>>>();
    count_kernel<<<EE / 256, 256, 0, s2>>>(ei);
    scan_kernel<<<1, 1024, 0, s2>>>();
    fill_kernel<<<EE / 256, 256, 0, s2>>>(ei);
    agg_kernel<<<NN, 96, 0, s2>>>(x, ei, ea);
    gemm_mma_kernel<true, 0, 0><<<gemmD, 256, 0, s2>>>(agg, nullptr, W1, b1, nullptr,
                                                       nullptr, t, DD, DD);
    gemm_mma_kernel<false, 0, 1><<<gemmD, 256, 0, s2>>>(t, nullptr, W2, b2, x, nullptr,
                                                        hl, DD, DD);
    bn_stats_kernel<<<NN / 128, DD, 0, s2>>>(hl, 0);
    bn_finalize_kernel<<<1, DD, 0, s2>>>(g1l, be1l, 0);

    // Attention branch (default)
    gemm_qkv_kernel<<<gemmQKV, 256>>>(x, Wq, bq, Wk, bk, Wv, bv, q, k, v);
    attn_mma_kernel<<<dim3(SSEQ / 128, HHEADS, BBATCH), 256, ATTN_SMEM>>>(q, k, v, o);
    gemm_mma_kernel<false, 0, 1><<<gemmD, 256>>>(o, nullptr, Wo, bo, x, nullptr, out,
                                                 DD, DD);
    bn_stats_kernel<<<NN / 128, DD>>>(out, 1);
    bn_finalize_kernel<<<1, DD>>>(g1a, be1a, 1);

    // ---- join ----
    cudaEventRecord(evJ, s2);
    cudaStreamWaitEvent(0, evJ, 0);

    // ---- FFN with fused combine + final BN ----
    // FF1: A = bn0(hl) + bn1(out)  -> t (relu)
    gemm_mma_kernel<true, 1, 0><<<gemmF, 256>>>(hl, out, Wf1, bf1, nullptr, nullptr, t,
                                                DD, FFDIM);
    // FF2: C = t @ Wf2 + bf2 + (bn0(hl) + bn1(out)) -> out
    gemm_mma_kernel<false, 0, 2><<<gemmD, 256>>>(t, nullptr, Wf2, bf2, hl, out, out,
                                                 FFDIM, DD);
    zero_stats_kernel<<<1, DD>>>();
    bn_stats_kernel<<<NN / 128, DD>>>(out, 0);
    bn_finalize_kernel<<<1, DD>>>(g2, be2, 0);
    bn_apply_kernel<<<EW_BLOCKS, 256>>>(out);
}

// round 17
// speedup vs baseline: 1.0658x; 1.0658x over previous
#include <cuda_runtime.h>
#include <cstdint>

// Problem constants
#define NN 32768
#define DD 384
#define EE 524288
#define BBATCH 32
#define SSEQ 1024
#define HHEADS 8
#define DHEAD 48
#define FFDIM 768
#define BN_EPS 1e-5f

#define MMA_TF32(c, a0, a1, a2, a3, b0, b1) \
    asm volatile( \
        "mma.sync.aligned.m16n8k8.row.col.f32.tf32.tf32.f32 " \
        "{%0,%1,%2,%3}, {%4,%5,%6,%7}, {%8,%9}, {%0,%1,%2,%3};" \
        : "+f"((c)[0]), "+f"((c)[1]), "+f"((c)[2]), "+f"((c)[3]) \
        : "r"(a0), "r"(a1), "r"(a2), "r"(a3), "r"(b0), "r"(b1))

// ---------------- device scratch ----------------
__device__ float g_agg[(size_t)NN * DD];
__device__ float g_hl[(size_t)NN * DD];
__device__ float g_t[(size_t)NN * FFDIM];
__device__ float g_q[(size_t)NN * DD];
__device__ float g_k[(size_t)NN * DD];
__device__ float g_v[(size_t)NN * DD];
__device__ float g_o[(size_t)NN * DD];
__device__ float g_sum[2 * DD];
__device__ float g_sq[2 * DD];
__device__ float g_scale[2 * DD];
__device__ float g_shift[2 * DD];
__device__ int g_cnt[NN];
__device__ int g_start[NN];
__device__ int g_cursor[NN];
__device__ int g_eid[EE];

// ---------------- tf32 mma.sync SGEMM: 128x128x16 per CTA, 8 warps ----------------
template <bool RELU, bool RES>
__global__ __launch_bounds__(256) void gemm_mma_kernel(
    const float* __restrict__ A, const float* __restrict__ W,
    const float* __restrict__ bias, const float* __restrict__ res,
    float* __restrict__ C, int K, int M) {
    __shared__ uint32_t Af[2][2][8][128];
    __shared__ uint32_t Bf[2][2][16][66];

    const int tid = threadIdx.x;
    const int lane = tid & 31;
    const int wid = tid >> 5;
    const int warpRow = wid >> 2;
    const int warpCol = wid & 3;
    const int colBase = blockIdx.x * 128;
    const size_t rowBase = (size_t)blockIdx.y * 128;

    float acc[4][4][4];
#pragma unroll
    for (int i = 0; i < 4; i++)
#pragma unroll
        for (int j = 0; j < 4; j++)
#pragma unroll
            for (int e = 0; e < 4; e++) acc[i][j][e] = 0.f;

    const int ar = tid >> 1;
    const int akq = (tid & 1) * 8;
    const int a_kk = akq >> 3;
    const int a_mt = ar >> 4;
    const int a_g = ar & 7;
    const int a_half = (ar >> 3) & 1;
    const int bkr = tid >> 4;
    const int bnq = (tid & 15) * 8;
    const int b_kk = bkr >> 3;
    const int b_c = bkr & 7;
    const int b_slot = (b_c >= 4) ? 1 : 0;
    const int b_cm = b_c & 3;

    const float* Ap = A + (rowBase + ar) * (size_t)K + akq;
    const float* Wp = W + (size_t)bkr * M + colBase + bnq;

    const int stages = K >> 4;
    float aR[8], bR[8];

    auto load_regs = [&](int s) {
        const float* Ap2 = Ap + s * 16;
        const float* Wp2 = Wp + (size_t)s * 16 * M;
        float4 t0 = *(const float4*)(Ap2);
        float4 t1 = *(const float4*)(Ap2 + 4);
        aR[0] = t0.x; aR[1] = t0.y; aR[2] = t0.z; aR[3] = t0.w;
        aR[4] = t1.x; aR[5] = t1.y; aR[6] = t1.z; aR[7] = t1.w;
        float4 u0 = *(const float4*)(Wp2);
        float4 u1 = *(const float4*)(Wp2 + 4);
        bR[0] = u0.x; bR[1] = u0.y; bR[2] = u0.z; bR[3] = u0.w;
        bR[4] = u1.x; bR[5] = u1.y; bR[6] = u1.z; bR[7] = u1.w;
    };
    auto store_stage = [&](int buf) {
#pragma unroll
        for (int j = 0; j < 8; j++) {
            int slot = ((j >= 4) ? 2 : 0) + a_half;
            if (a_kk) slot ^= 2;
            int lp = a_g + (j & 3) * 8;
            Af[buf][a_kk][a_mt][lp * 4 + slot] = __float_as_uint(aR[j]);
        }
#pragma unroll
        for (int j = 0; j < 8; j++) {
            int nl = bnq + j;
            Bf[buf][b_kk][nl >> 3][((nl & 7) * 4 + b_cm) * 2 + b_slot] =
                __float_as_uint(bR[j]);
        }
    };

    load_regs(0);
    store_stage(0);
    if (stages > 1) load_regs(1);
    __syncthreads();

    const int rp = (lane >> 2) + (lane & 3) * 8;

    for (int s = 0; s < stages; s++) {
        const int cur = s & 1;
        if (s + 1 < stages) store_stage(1 - cur);
        if (s + 2 < stages) load_regs(s + 2);
#pragma unroll
        for (int kk = 0; kk < 2; kk++) {
            uint32_t af[4][4];
            uint32_t bf[4][2];
#pragma unroll
            for (int mi = 0; mi < 4; mi++)
                *(uint4*)af[mi] = *(const uint4*)&Af[cur][kk][warpRow * 4 + mi][rp * 4];
#pragma unroll
            for (int ni = 0; ni < 4; ni++)
                *(uint2*)bf[ni] = *(const uint2*)&Bf[cur][kk][warpCol * 4 + ni][lane * 2];
#pragma unroll
            for (int mi = 0; mi < 4; mi++)
#pragma unroll
                for (int ni = 0; ni < 4; ni++) {
                    if (kk == 0) {
                        MMA_TF32(acc[mi][ni], af[mi][0], af[mi][1], af[mi][2], af[mi][3],
                                 bf[ni][0], bf[ni][1]);
                    } else {
                        MMA_TF32(acc[mi][ni], af[mi][2], af[mi][3], af[mi][0], af[mi][1],
                                 bf[ni][0], bf[ni][1]);
                    }
                }
        }
        __syncthreads();
    }

    const int g = lane >> 2, cq = lane & 3;
#pragma unroll
    for (int mi = 0; mi < 4; mi++) {
        size_t row0 = rowBase + warpRow * 64 + mi * 16 + g;
        size_t row1 = row0 + 8;
#pragma unroll
        for (int ni = 0; ni < 4; ni++) {
            int col = colBase + warpCol * 32 + ni * 8 + cq * 2;
            float2 bi = *(const float2*)(bias + col);
            float o0 = acc[mi][ni][0] + bi.x;
            float o1 = acc[mi][ni][1] + bi.y;
            float o2 = acc[mi][ni][2] + bi.x;
            float o3 = acc[mi][ni][3] + bi.y;
            if (RELU) {
                o0 = fmaxf(o0, 0.f); o1 = fmaxf(o1, 0.f);
                o2 = fmaxf(o2, 0.f); o3 = fmaxf(o3, 0.f);
            }
            if (RES) {
                float2 r0 = *(const float2*)(res + row0 * (size_t)M + col);
                float2 r1 = *(const float2*)(res + row1 * (size_t)M + col);
                o0 += r0.x; o1 += r0.y; o2 += r1.x; o3 += r1.y;
            }
            *(float2*)(C + row0 * (size_t)M + col) = make_float2(o0, o1);
            *(float2*)(C + row1 * (size_t)M + col) = make_float2(o2, o3);
        }
    }
}

// ---------------- tf32 mma flash attention ----------------
#define ATTN_SMEM 57344
__global__ __launch_bounds__(256) void attn_mma_kernel(
    const float* __restrict__ q, const float* __restrict__ k,
    const float* __restrict__ v, float* __restrict__ o) {
    extern __shared__ uint32_t sm[];
    const int tid = threadIdx.x;
    const int lane = tid & 31, wid = tid >> 5;
    const int g = lane >> 2, cq = lane & 3;
    uint32_t* Kf = sm;
    uint32_t* Vf = sm + 3072;
    uint32_t* Pf = sm + 6144 + wid * 1024;

    const int b = blockIdx.z, h = blockIdx.y, qt = blockIdx.x;
    const float rs = 0.14433756729740643f;

    uint32_t qf[6][4];
    {
        const float* qp0 =
            q + ((size_t)(b * SSEQ + qt * 128 + wid * 16 + g)) * DD + h * DHEAD;
        const float* qp1 = qp0 + 8 * DD;
#pragma unroll
        for (int kc = 0; kc < 6; kc++) {
            qf[kc][0] = __float_as_uint(qp0[kc * 8 + cq] * rs);
            qf[kc][1] = __float_as_uint(qp1[kc * 8 + cq] * rs);
            qf[kc][2] = __float_as_uint(qp0[kc * 8 + cq + 4] * rs);
            qf[kc][3] = __float_as_uint(qp1[kc * 8 + cq + 4] * rs);
        }
    }
    float oa[6][4];
#pragma unroll
    for (int i = 0; i < 6; i++)
#pragma unroll
        for (int e = 0; e < 4; e++) oa[i][e] = 0.f;
    float l0 = 0.f, l1 = 0.f;

    const int lr = tid >> 2;
    const int ld = (tid & 3) * 12;
    const size_t kvbase = (size_t)(b * SSEQ) * DD + h * DHEAD;

    float kreg[12], vreg[12];
    {
        const float* kp = k + kvbase + (size_t)lr * DD + ld;
        const float* vp = v + kvbase + (size_t)lr * DD + ld;
#pragma unroll
        for (int j = 0; j < 3; j++) {
            *(float4*)&kreg[j * 4] = *(const float4*)(kp + j * 4);
            *(float4*)&vreg[j * 4] = *(const float4*)(vp + j * 4);
        }
    }

    for (int kt = 0; kt < SSEQ; kt += 64) {
        __syncthreads();
#pragma unroll
        for (int j = 0; j < 12; j++) {
            int d = ld + j;
            Kf[((d >> 3) * 8 + (lr >> 3)) * 64 + ((lr & 7) * 4 + (d & 3)) * 2 +
               ((d & 7) >= 4)] = __float_as_uint(kreg[j]);
            Vf[((lr >> 3) * 6 + (d >> 3)) * 64 + ((d & 7) * 4 + (lr & 3)) * 2 +
               ((lr & 7) >= 4)] = __float_as_uint(vreg[j]);
        }
        __syncthreads();
        if (kt + 64 < SSEQ) {
            const float* kp = k + kvbase + (size_t)(kt + 64 + lr) * DD + ld;
            const float* vp = v + kvbase + (size_t)(kt + 64 + lr) * DD + ld;
#pragma unroll
            for (int j = 0; j < 3; j++) {
                *(float4*)&kreg[j * 4] = *(const float4*)(kp + j * 4);
                *(float4*)&vreg[j * 4] = *(const float4*)(vp + j * 4);
            }
        }
#pragma unroll
        for (int nt = 0; nt < 8; nt++) {
            float c[4] = {0.f, 0.f, 0.f, 0.f};
#pragma unroll
            for (int kc = 0; kc < 6; kc++) {
                uint2 kb = *(const uint2*)&Kf[(kc * 8 + nt) * 64 + lane * 2];
                MMA_TF32(c, qf[kc][0], qf[kc][1], qf[kc][2], qf[kc][3], kb.x, kb.y);
            }
            float p0 = __expf(c[0]), p1 = __expf(c[1]);
            float p2 = __expf(c[2]), p3 = __expf(c[3]);
            l0 += p0 + p1;
            l1 += p2 + p3;
            int pb = nt * 128 + ((cq < 2) ? 0 : 64) + 4 * g + ((2 * cq) & 3);
            uint2 w0, w1;
            w0.x = __float_as_uint(p0); w0.y = __float_as_uint(p1);
            w1.x = __float_as_uint(p2); w1.y = __float_as_uint(p3);
            *(uint2*)&Pf[pb] = w0;
            *(uint2*)&Pf[pb + 32] = w1;
        }
        __syncwarp();
#pragma unroll
        for (int kc = 0; kc < 8; kc++) {
            uint32_t pa0 = Pf[kc * 128 + lane];
            uint32_t pa1 = Pf[kc * 128 + 32 + lane];
            uint32_t pa2 = Pf[kc * 128 + 64 + lane];
            uint32_t pa3 = Pf[kc * 128 + 96 + lane];
#pragma unroll
            for (int nt2 = 0; nt2 < 6; nt2++) {
                uint2 vb = *(const uint2*)&Vf[(kc * 6 + nt2) * 64 + lane * 2];
                MMA_TF32(oa[nt2], pa0, pa1, pa2, pa3, vb.x, vb.y);
            }
        }
    }

    l0 += __shfl_xor_sync(0xffffffff, l0, 1);
    l0 += __shfl_xor_sync(0xffffffff, l0, 2);
    l1 += __shfl_xor_sync(0xffffffff, l1, 1);
    l1 += __shfl_xor_sync(0xffffffff, l1, 2);
    float i0 = 1.f / l0, i1 = 1.f / l1;
    float* op0 = o + ((size_t)(b * SSEQ + qt * 128 + wid * 16 + g)) * DD + h * DHEAD;
    float* op1 = op0 + 8 * DD;
#pragma unroll
    for (int nt2 = 0; nt2 < 6; nt2++) {
        int col = nt2 * 8 + 2 * cq;
        *(float2*)(op0 + col) = make_float2(oa[nt2][0] * i0, oa[nt2][1] * i0);
        *(float2*)(op1 + col) = make_float2(oa[nt2][2] * i1, oa[nt2][3] * i1);
    }
}

// ---------------- CSR build ----------------
__global__ void zero_cnt_kernel() {
    int i = blockIdx.x * blockDim.x + threadIdx.x;
    g_cnt[i] = 0;
}
__global__ void count_kernel(const int* __restrict__ ei) {
    int e = blockIdx.x * blockDim.x + threadIdx.x;
    atomicAdd(&g_cnt[ei[EE + e]], 1);
}
__global__ void scan_kernel() {
    __shared__ int sh[1024];
    int t = threadIdx.x;
    int base = t * 32;
    int local[32];
    int s = 0;
#pragma unroll
    for (int i = 0; i < 8; i++) {
        int4 c4 = *(const int4*)&g_cnt[base + i * 4];
        local[i * 4 + 0] = c4.x; local[i * 4 + 1] = c4.y;
        local[i * 4 + 2] = c4.z; local[i * 4 + 3] = c4.w;
        s += c4.x + c4.y + c4.z + c4.w;
    }
    sh[t] = s;
    __syncthreads();
    for (int off = 1; off < 1024; off <<= 1) {
        int v = sh[t];
        int add = (t >= off) ? sh[t - off] : 0;
        __syncthreads();
        sh[t] = v + add;
        __syncthreads();
    }
    int run = sh[t] - s;
#pragma unroll
    for (int i = 0; i < 8; i++) {
        int4 o4;
        o4.x = run; run += local[i * 4 + 0];
        o4.y = run; run += local[i * 4 + 1];
        o4.z = run; run += local[i * 4 + 2];
        o4.w = run; run += local[i * 4 + 3];
        *(int4*)&g_start[base + i * 4] = o4;
        *(int4*)&g_cursor[base + i * 4] = o4;
    }
}
__global__ void fill_kernel(const int* __restrict__ ei) {
    int e = blockIdx.x * blockDim.x + threadIdx.x;
    int d = ei[EE + e];
    int slot = atomicAdd(&g_cursor[d], 1);
    g_eid[slot] = e;
}

// 2 nodes per CTA with UNIFORM barrier count: both halves loop to cntMax.
__global__ __launch_bounds__(192) void agg_kernel(const float* __restrict__ x,
                                                  const int* __restrict__ ei,
                                                  const float* __restrict__ ea) {
    __shared__ int s_eid[2][128];
    __shared__ int s_src[2][128];
    __shared__ int s_cnt[2];
    const int half = threadIdx.x / 96;  // 0 or 1
    const int g = threadIdx.x % 96;
    const int node = blockIdx.x * 2 + half;
    const int start = g_start[node];
    const int cnt = g_cnt[node];
    if (g == 0) s_cnt[half] = cnt;
    __syncthreads();
    const int cntMax = max(s_cnt[0], s_cnt[1]);
    float4 acc = *(const float4*)(x + (size_t)node * DD + g * 4);
    for (int baseI = 0; baseI < cntMax; baseI += 128) {
        int chunk = min(cnt - baseI, 128);  // may be <= 0 for this half
        __syncthreads();
        for (int i = g; i < chunk; i += 96) {
            int e = g_eid[start + baseI + i];
            s_eid[half][i] = e;
            s_src[half][i] = ei[e];
        }
        __syncthreads();
#pragma unroll 4
        for (int i = 0; i < chunk; i++) {
            float4 xv = *(const float4*)(x + (size_t)s_src[half][i] * DD + g * 4);
            float4 av = *(const float4*)(ea + (size_t)s_eid[half][i] * DD + g * 4);
            acc.x += fmaxf(xv.x + av.x, 0.f);
            acc.y += fmaxf(xv.y + av.y, 0.f);
            acc.z += fmaxf(xv.z + av.z, 0.f);
            acc.w += fmaxf(xv.w + av.w, 0.f);
        }
    }
    *(float4*)(g_agg + (size_t)node * DD + g * 4) = acc;
}

// ---------------- BatchNorm ----------------
__global__ void zero_stats2_kernel() {
    int c = blockIdx.x * blockDim.x + threadIdx.x;
    g_sum[c] = 0.f;
    g_sq[c] = 0.f;
}
__global__ void zero_stats_kernel() {
    int c = threadIdx.x;
    g_sum[c] = 0.f;
    g_sq[c] = 0.f;
}
__global__ void bn_stats_kernel(const float* __restrict__ h, int idx) {
    int c = threadIdx.x;
    const float* p = h + (size_t)blockIdx.x * 128 * DD + c;
    float s = 0.f, q = 0.f;
#pragma unroll 4
    for (int r = 0; r < 128; r++) {
        float v = p[(size_t)r * DD];
        s += v;
        q = fmaf(v, v, q);
    }
    atomicAdd(&g_sum[idx * DD + c], s);
    atomicAdd(&g_sq[idx * DD + c], q);
}
__global__ void bn_finalize_kernel(const float* __restrict__ gamma,
                                   const float* __restrict__ beta, int idx) {
    int c = threadIdx.x;
    float mean = g_sum[idx * DD + c] * (1.f / NN);
    float var = g_sq[idx * DD + c] * (1.f / NN) - mean * mean;
    float sc = gamma[c] * rsqrtf(var + BN_EPS);
    g_scale[idx * DD + c] = sc;
    g_shift[idx * DD + c] = beta[c] - mean * sc;
}
__global__ void combine_kernel(const float* __restrict__ ha) {
    size_t gid = (size_t)blockIdx.x * blockDim.x + threadIdx.x;
    int c = (int)(gid % (DD / 4)) << 2;
    float4 a = ((float4*)g_hl)[gid];
    float4 b = ((const float4*)ha)[gid];
    float4 sA = *(const float4*)&g_scale[c];
    float4 hA = *(const float4*)&g_shift[c];
    float4 sB = *(const float4*)&g_scale[DD + c];
    float4 hB = *(const float4*)&g_shift[DD + c];
    float4 o;
    o.x = a.x * sA.x + hA.x + b.x * sB.x + hB.x;
    o.y = a.y * sA.y + hA.y + b.y * sB.y + hB.y;
    o.z = a.z * sA.z + hA.z + b.z * sB.z + hB.z;
    o.w = a.w * sA.w + hA.w + b.w * sB.w + hB.w;
    ((float4*)g_hl)[gid] = o;
}
__global__ void bn_apply_kernel(float* __restrict__ h) {
    size_t gid = (size_t)blockIdx.x * blockDim.x + threadIdx.x;
    int c = (int)(gid % (DD / 4)) << 2;
    float4 v = ((float4*)h)[gid];
    float4 s = *(const float4*)&g_scale[c];
    float4 sh = *(const float4*)&g_shift[c];
    v.x = v.x * s.x + sh.x;
    v.y = v.y * s.y + sh.y;
    v.z = v.z * s.z + sh.z;
    v.w = v.w * s.w + sh.w;
    ((float4*)h)[gid] = v;
}

// ---------------- launch ----------------
extern "C" void kernel_launch(void* const* d_in, const int* in_sizes, int n_in,
                              void* d_out, int out_size) {
    const float* x = (const float*)d_in[0];
    const int* ei = (const int*)d_in[1];
    const float* ea = (const float*)d_in[2];
    const float* W1 = (const float*)d_in[4];
    const float* b1 = (const float*)d_in[5];
    const float* W2 = (const float*)d_in[6];
    const float* b2 = (const float*)d_in[7];
    const float* g1l = (const float*)d_in[8];
    const float* be1l = (const float*)d_in[9];
    const float* Wq = (const float*)d_in[10];
    const float* bq = (const float*)d_in[11];
    const float* Wk = (const float*)d_in[12];
    const float* bk = (const float*)d_in[13];
    const float* Wv = (const float*)d_in[14];
    const float* bv = (const float*)d_in[15];
    const float* Wo = (const float*)d_in[16];
    const float* bo = (const float*)d_in[17];
    const float* g1a = (const float*)d_in[18];
    const float* be1a = (const float*)d_in[19];
    const float* Wf1 = (const float*)d_in[20];
    const float* bf1 = (const float*)d_in[21];
    const float* Wf2 = (const float*)d_in[22];
    const float* bf2 = (const float*)d_in[23];
    const float* g2 = (const float*)d_in[24];
    const float* be2 = (const float*)d_in[25];
    float* out = (float*)d_out;

    float *agg, *hl, *t, *q, *k, *v, *o;
    cudaGetSymbolAddress((void**)&agg, g_agg);
    cudaGetSymbolAddress((void**)&hl, g_hl);
    cudaGetSymbolAddress((void**)&t, g_t);
    cudaGetSymbolAddress((void**)&q, g_q);
    cudaGetSymbolAddress((void**)&k, g_k);
    cudaGetSymbolAddress((void**)&v, g_v);
    cudaGetSymbolAddress((void**)&o, g_o);

    cudaFuncSetAttribute(attn_mma_kernel,
                         cudaFuncAttributeMaxDynamicSharedMemorySize, ATTN_SMEM);

    static cudaStream_t s2 = nullptr;
    static cudaEvent_t evF = nullptr, evJ = nullptr;
    if (s2 == nullptr) {
        cudaStreamCreate(&s2);
        cudaEventCreateWithFlags(&evF, cudaEventDisableTiming);
        cudaEventCreateWithFlags(&evJ, cudaEventDisableTiming);
    }

    const int EW_BLOCKS = (NN * DD / 4) / 256;
    const dim3 gemmD(DD / 128, NN / 128);    // (3, 256)
    const dim3 gemmF(FFDIM / 128, NN / 128); // (6, 256)

    zero_stats2_kernel<<<2, DD>>>();

    // ---- fork: GINE branch on s2, attention branch on default stream ----
    cudaEventRecord(evF, 0);
    cudaStreamWaitEvent(s2, evF, 0);

    // GINE branch (s2): CSR + agg + MLP + BN stats (slot 0)
    zero_cnt_kernel<<<NN / 256, 256, 0, s2>>>();
    count_kernel<<<EE / 256, 256, 0, s2>>>(ei);
    scan_kernel<<<1, 1024, 0, s2>>>();
    fill_kernel<<<EE / 256, 256, 0, s2>>>(ei);
    agg_kernel<<<NN / 2, 192, 0, s2>>>(x, ei, ea);
    gemm_mma_kernel<true, false><<<gemmD, 256, 0, s2>>>(agg, W1, b1, nullptr, t, DD, DD);
    gemm_mma_kernel<false, true><<<gemmD, 256, 0, s2>>>(t, W2, b2, x, hl, DD, DD);
    bn_stats_kernel<<<NN / 128, DD, 0, s2>>>(hl, 0);
    bn_finalize_kernel<<<1, DD, 0, s2>>>(g1l, be1l, 0);

    // Attention branch (default): QKV + attn + Wo + BN stats (slot 1)
    gemm_mma_kernel<false, false><<<gemmD, 256>>>(x, Wq, bq, nullptr, q, DD, DD);
    gemm_mma_kernel<false, false><<<gemmD, 256>>>(x, Wk, bk, nullptr, k, DD, DD);
    gemm_mma_kernel<false, false><<<gemmD, 256>>>(x, Wv, bv, nullptr, v, DD, DD);
    attn_mma_kernel<<<dim3(SSEQ / 128, HHEADS, BBATCH), 256, ATTN_SMEM>>>(q, k, v, o);
    gemm_mma_kernel<false, true><<<gemmD, 256>>>(o, Wo, bo, x, out, DD, DD);
    bn_stats_kernel<<<NN / 128, DD>>>(out, 1);
    bn_finalize_kernel<<<1, DD>>>(g1a, be1a, 1);

    // ---- join ----
    cudaEventRecord(evJ, s2);
    cudaStreamWaitEvent(0, evJ, 0);

    // ---- combine + FFN + final BN (default stream) ----
    combine_kernel<<<EW_BLOCKS, 256>>>(out);
    zero_stats_kernel<<<1, DD>>>();
    gemm_mma_kernel<true, false><<<gemmF, 256>>>(hl, Wf1, bf1, nullptr, t, DD, FFDIM);
    gemm_mma_kernel<false, true><<<gemmD, 256>>>(t, Wf2, bf2, hl, out, FFDIM, DD);
    bn_stats_kernel<<<NN / 128, DD>>>(out, 0);
    bn_finalize_kernel<<<1, DD>>>(g2, be2, 0);
    bn_apply_kernel<<<EW_BLOCKS, 256>>>(out);
}